// round 9
// baseline (speedup 1.0000x reference)
#include <cuda_runtime.h>
#include <math_constants.h>
#include <stdint.h>

// MulticlassNMS v4 — two launches:
//  1) transpose_kernel: scores[n,c] -> g_T[cls][i] (fg classes), resets arrival ctr
//  2) fused_kernel (1 block/class, 512 thr): coalesced compact via block scan,
//     shfl-fused bitonic sort, chunked greedy NMS (64-wide, sparse resolve);
//     last block to finish runs the global top-300 + output phase in-place.

#define MAXCLS 128
#define MAXNN  8192
#define MAXK   300
#define TA     512
#define SBOXN  1024
#define GCAP   512

__device__ float    g_T[MAXCLS * MAXNN];
__device__ float    g_ks[MAXCLS * MAXK];
__device__ int      g_kb[MAXCLS * MAXK];
__device__ int      g_kc[MAXCLS];
__device__ unsigned g_arrive;

// exact IoU>thr: multiply filter, __fdiv_rn fallback in ~1e-4 boundary band
__device__ __forceinline__ bool iou_gt(const float4 a, float aa,
                                       const float4 b, float ba,
                                       float thr, float thrLo, float thrHi)
{
    float ix1 = fmaxf(a.x, b.x), iy1 = fmaxf(a.y, b.y);
    float ix2 = fminf(a.z, b.z), iy2 = fminf(a.w, b.w);
    float iw = ix2 - ix1, ih = iy2 - iy1;
    if (iw <= 0.f || ih <= 0.f) return false;
    float inter = iw * ih;
    float u = (aa + ba) - inter;
    if (inter > thrHi * u) return true;
    if (inter < thrLo * u) return false;
    return __fdiv_rn(inter, u) > thr;
}

// ---------------- prep: transpose scores + reset arrival counter ----------
__global__ void transpose_kernel(const float* __restrict__ scores, int n, int c)
{
    __shared__ float tile[32][33];
    int j0 = blockIdx.x * 32, i0 = blockIdx.y * 32;
    int tx = threadIdx.x, ty = threadIdx.y;
    #pragma unroll
    for (int k = 0; k < 32; k += 8) {
        int i = i0 + ty + k, j = j0 + tx;
        tile[ty + k][tx] = (i < n && j < c) ? scores[(size_t)i * c + j] : 0.f;
    }
    __syncthreads();
    #pragma unroll
    for (int k = 0; k < 32; k += 8) {
        int jt = j0 + ty + k, it = i0 + tx;
        if (jt >= 1 && jt < c && it < n)
            g_T[(size_t)(jt - 1) * n + it] = tile[tx][ty + k];
    }
    if (blockIdx.x == 0 && blockIdx.y == 0 && tx == 0 && ty == 0) g_arrive = 0;
}

// ---------------- fused per-class NMS + (last block) global top-300 -------
__global__ __launch_bounds__(TA)
void fused_kernel(const float4* __restrict__ bb4,
                  const float* __restrict__ confp,
                  const float* __restrict__ nmsp,
                  float* __restrict__ out,
                  int n, int nc)
{
    extern __shared__ unsigned char smraw[];
    // phase-A layout
    unsigned long long* skey   = (unsigned long long*)smraw;        // [8192]
    float4*             sbox   = (float4*)(smraw + 65536);          // [1024]
    float4*             kbox   = (float4*)(smraw + 81920);          // [304]
    float4*             cbox   = (float4*)(smraw + 86784);          // [64]
    float*              sarea  = (float*)(smraw + 87808);           // [1024]
    float*              karea  = (float*)(smraw + 91904);           // [304]
    float*              carea  = (float*)(smraw + 93120);           // [64]
    unsigned*           sIntra = (unsigned*)(smraw + 93376);        // [128]
    unsigned*           snzw   = (unsigned*)(smraw + 93888);        // [16]
    unsigned*           sSup32 = (unsigned*)(smraw + 93952);        // [2]

    __shared__ int wsum[16];
    __shared__ unsigned long long sKeptMask;
    __shared__ unsigned sLast;

    const int tid  = threadIdx.x;
    const int wid  = tid >> 5, lane = tid & 31;
    const int cls  = blockIdx.x;
    const float conf  = *confp;
    const float thr   = *nmsp;
    const float thrLo = thr * 0.9999f;
    const float thrHi = thr * 1.0001f;
    const unsigned FULL = 0xffffffffu;

    // ---- compaction: count -> block scan -> scatter (coalesced g_T reads) --
    const float* Tc = g_T + (size_t)cls * n;
    int cnt = 0;
    for (int i = tid; i < n; i += TA) cnt += (Tc[i] > conf) ? 1 : 0;
    int x = cnt;
    #pragma unroll
    for (int o = 1; o < 32; o <<= 1) {
        int y = __shfl_up_sync(FULL, x, o);
        if (lane >= o) x += y;
    }
    if (lane == 31) wsum[wid] = x;
    __syncthreads();
    if (tid < 32) {
        int w = (tid < 16) ? wsum[tid] : 0;
        #pragma unroll
        for (int o = 1; o < 16; o <<= 1) {
            int y = __shfl_up_sync(FULL, w, o);
            if (tid >= o) w += y;
        }
        if (tid < 16) wsum[tid] = w;
    }
    __syncthreads();
    int off = x - cnt + ((wid > 0) ? wsum[wid - 1] : 0);
    const int M = wsum[15];
    for (int i = tid; i < n; i += TA) {
        float s = Tc[i];
        if (s > conf) {
            skey[off] = ((unsigned long long)__float_as_uint(s) << 32) | (unsigned)i;
            off++;
        }
    }
    int P = 256; while (P < M) P <<= 1;
    __syncthreads();
    for (int p = M + tid; p < P; p += TA) skey[p] = 0ULL;
    __syncthreads();

    // ---- shfl-fused bitonic sort (desc; ties -> larger idx first) ----------
    // shared+barrier only for j>=256; j=8..128 via shfl butterflies; j<=4 regs.
    for (int k = 2; k <= P; k <<= 1) {
        for (int j = k >> 1; j >= 256; j >>= 1) {
            for (int p = tid; p < P; p += TA) {
                int q = p ^ j;
                if (q > p) {
                    unsigned long long a = skey[p], b = skey[q];
                    bool dirDesc = ((p & k) == 0);
                    if (dirDesc ? (a < b) : (a > b)) { skey[p] = b; skey[q] = a; }
                }
            }
            __syncthreads();
        }
        for (int base = tid * 8; base < P; base += TA * 8) {
            unsigned long long v[8];
            #pragma unroll
            for (int a = 0; a < 8; a++) v[a] = skey[base + a];
            const bool up = ((base & k) == 0);       // valid for k>=16 (only used then)
            int jtop = (k >> 1 < 128) ? (k >> 1) : 128;
            for (int j = jtop; j >= 8; j >>= 1) {
                int tj = j >> 3;
                bool keepMax = (up == ((tid & tj) == 0));
                #pragma unroll
                for (int a = 0; a < 8; a++) {
                    unsigned long long pv = __shfl_xor_sync(FULL, v[a], tj);
                    if (keepMax ? (pv > v[a]) : (pv < v[a])) v[a] = pv;
                }
            }
            int j0 = (k >> 1 < 4) ? (k >> 1) : 4;
            for (int j = j0; j > 0; j >>= 1) {
                #pragma unroll
                for (int a = 0; a < 8; a++) {
                    int b = a ^ j;
                    if (b > a) {
                        bool dd = (((base + a) & k) == 0);
                        unsigned long long xx = v[a], yy = v[b];
                        if (dd ? (xx < yy) : (xx > yy)) { v[a] = yy; v[b] = xx; }
                    }
                }
            }
            #pragma unroll
            for (int a = 0; a < 8; a++) skey[base + a] = v[a];
        }
        __syncthreads();
    }

    // ---- prefetch top candidates' boxes/areas ----
    const int PF = min(M, SBOXN);
    for (int p = tid; p < PF; p += TA) {
        float4 b = bb4[(unsigned)(skey[p] & 0xffffffffu)];
        sbox[p]  = b;
        sarea[p] = (b.z - b.x) * (b.w - b.y);
    }
    __syncthreads();

    // ---- chunked greedy NMS (64-wide chunks) ----
    int pos = 0, nKept = 0;
    while (pos < M && nKept < MAXK) {
        const int nv = min(64, M - pos);

        if (tid < 64) {
            int cl2 = pos + tid;
            float4 cb = make_float4(0.f, 0.f, 0.f, 0.f);
            if (cl2 < M)
                cb = (cl2 < PF) ? sbox[cl2]
                                : bb4[(unsigned)(skey[cl2] & 0xffffffffu)];
            cbox[tid]  = cb;
            carea[tid] = (cb.z - cb.x) * (cb.w - cb.y);
            if (tid < 2)  sSup32[tid] = 0;
            if (tid < 16) snzw[tid]   = 0;
        }
        __syncthreads();

        {
            // vs-kept (unroll x4, independent accumulators)
            int cg = wid & 1;
            int cc = (cg << 5) | lane;
            float4 cb = cbox[cc];
            float  ca = carea[cc];
            bool s0 = false, s1 = false, s2 = false, s3 = false;
            int k2 = wid >> 1;
            for (; k2 + 24 < nKept; k2 += 32) {
                s0 |= iou_gt(kbox[k2],      karea[k2],      cb, ca, thr, thrLo, thrHi);
                s1 |= iou_gt(kbox[k2 + 8],  karea[k2 + 8],  cb, ca, thr, thrLo, thrHi);
                s2 |= iou_gt(kbox[k2 + 16], karea[k2 + 16], cb, ca, thr, thrLo, thrHi);
                s3 |= iou_gt(kbox[k2 + 24], karea[k2 + 24], cb, ca, thr, thrLo, thrHi);
            }
            for (; k2 < nKept; k2 += 8)
                s0 |= iou_gt(kbox[k2], karea[k2], cb, ca, thr, thrLo, thrHi);
            bool sup = s0 | s1 | s2 | s3;
            unsigned bm = __ballot_sync(FULL, sup);
            if (lane == 0 && bm) atomicOr(&sSup32[cg], bm);

            // intra-chunk matrix rows (warp w owns rows 4w..4w+3)
            unsigned nzm = 0;
            #pragma unroll
            for (int r0 = 0; r0 < 4; r0++) {
                int r = (wid << 2) + r0;
                float4 rb = cbox[r];
                float  ra = carea[r];
                #pragma unroll
                for (int g = 0; g < 2; g++) {
                    int col = (g << 5) | lane;
                    bool pr = (col > r) &&
                              iou_gt(rb, ra, cbox[col], carea[col], thr, thrLo, thrHi);
                    unsigned w2 = __ballot_sync(FULL, pr);
                    if (lane == 0) {
                        sIntra[r * 2 + g] = w2;
                        if (w2) nzm |= 1u << (r0 * 2 + g);
                    }
                }
            }
            if (lane == 0) snzw[wid] = nzm;
        }
        __syncthreads();

        if (tid == 0) {
            unsigned long long valid = (nv >= 64) ? ~0ULL : ((1ULL << nv) - 1ULL);
            unsigned long long sup = (((unsigned long long)sSup32[1] << 32) |
                                       sSup32[0]) | ~valid;
            unsigned long long nz = 0;
            #pragma unroll
            for (int w = 0; w < 16; w++) {
                unsigned mm = snzw[w];
                unsigned rowbits = 0;
                #pragma unroll
                for (int r0 = 0; r0 < 4; r0++)
                    if (mm & (3u << (2 * r0))) rowbits |= 1u << r0;
                nz |= (unsigned long long)rowbits << (4 * w);
            }
            unsigned long long kept = 0;
            int prev = 0;
            while (nz) {
                int i = __ffsll((long long)nz) - 1;
                nz &= nz - 1;
                unsigned long long upto  = (i >= 63) ? ~0ULL : ((1ULL << (i + 1)) - 1ULL);
                unsigned long long fromp = (~0ULL) << prev;
                kept |= ~sup & upto & fromp;
                if (!((sup >> i) & 1ULL)) {
                    unsigned long long row =
                        (((unsigned long long)sIntra[2 * i + 1]) << 32) | sIntra[2 * i];
                    sup |= row;
                }
                prev = i + 1;
            }
            unsigned long long fromp = (prev >= 64) ? 0ULL : ((~0ULL) << prev);
            kept |= ~sup & fromp;
            sKeptMask = kept & valid;
        }
        __syncthreads();

        unsigned long long kept = sKeptMask;
        if (tid < 64) {
            bool mk = (kept >> tid) & 1ULL;
            int before = __popcll(kept & ((1ULL << tid) - 1ULL));
            int myPos  = nKept + before;
            if (mk && myPos < MAXK) {
                kbox[myPos]  = cbox[tid];
                karea[myPos] = carea[tid];
                unsigned long long kk = skey[pos + tid];
                g_ks[cls * MAXK + myPos] = __uint_as_float((unsigned)(kk >> 32));
                g_kb[cls * MAXK + myPos] = (int)(unsigned)(kk & 0xffffffffu);
            }
        }
        int nk = nKept + __popcll(kept);
        nKept = (nk > MAXK) ? MAXK : nk;
        pos  += 64;
    }

    for (int p = nKept + tid; p < MAXK; p += TA) g_ks[cls * MAXK + p] = 0.f;
    if (tid == 0) g_kc[cls] = nKept;

    // ---- arrival; last block runs the global top-300 phase -----------------
    __threadfence();
    __syncthreads();
    if (tid == 0)
        sLast = (atomicAdd(&g_arrive, 1) == (unsigned)(gridDim.x - 1)) ? 1u : 0u;
    __syncthreads();
    if (!sLast) return;
    __threadfence();

    // phase-B layout (overlaps phase-A shared)
    float*              sval   = (float*)smraw;                     // [24000]
    unsigned long long* gkey   = (unsigned long long*)(smraw + 96000); // [512]
    int*                hist   = (int*)(smraw + 100096);            // [2048]
    int*                schunk = (int*)(smraw + 108288);            // [256]

    __shared__ int   sTot, sGc, sDone, sAbove, smaxbits;
    __shared__ float sLo, sHi, sCut;

    const int total_slots = nc * MAXK;

    if (tid == 0) { sTot = 0; sDone = 0; sAbove = 0; smaxbits = 0; sGc = 0; }
    __syncthreads();
    if (tid < nc) atomicAdd(&sTot, g_kc[tid]);

    float m = 0.f;
    for (int s = tid; s < total_slots; s += TA) {
        float v = g_ks[s];
        sval[s] = v;
        m = fmaxf(m, v);
    }
    for (int o = 16; o; o >>= 1) m = fmaxf(m, __shfl_xor_sync(FULL, m, o));
    if (lane == 0 && m > 0.f) atomicMax(&smaxbits, __float_as_int(m));
    __syncthreads();

    if (tid == 0) {
        sLo = conf;
        sHi = __int_as_float(smaxbits) * 1.0000002f + 1e-30f;
        if (sTot <= MAXK) { sCut = 0.f; sDone = 1; }
    }
    __syncthreads();

    for (int lev = 0; lev < 6; lev++) {
        if (sDone) break;
        for (int b = tid; b < 2048; b += TA) hist[b] = 0;
        __syncthreads();
        float L = sLo, H = sHi;
        float scale = 2048.0f / (H - L);
        for (int s = tid; s < total_slots; s += TA) {
            float v = sval[s];
            if (v > conf && v >= L && v < H) {
                int bin = (int)((v - L) * scale);
                bin = max(0, min(2047, bin));
                atomicAdd(&hist[bin], 1);
            }
        }
        __syncthreads();
        if (tid < 256) {
            int sum = 0;
            for (int b = tid * 8; b < tid * 8 + 8; b++) sum += hist[b];
            schunk[tid] = sum;
        }
        __syncthreads();
        if (tid == 0) {
            int acc = sAbove, bstar = -1;
            for (int ch = 255; ch >= 0 && bstar < 0; ch--) {
                if (acc + schunk[ch] < MAXK) { acc += schunk[ch]; }
                else {
                    for (int b = ch * 8 + 7; b >= ch * 8; b--) {
                        if (acc + hist[b] < MAXK) acc += hist[b];
                        else { bstar = b; break; }
                    }
                }
            }
            float w    = (H - L) / 2048.0f;
            float cutv = L + bstar * w;
            bool collapsed = !(w > 0.f) || (L + w == L);
            if (acc + hist[bstar] <= GCAP || lev == 5 || collapsed) {
                float cut = cutv;
                if (cut > 0.f) cut = __uint_as_float(__float_as_uint(cut) - 2);
                sCut = cut; sDone = 1;
            } else {
                sAbove = acc;
                sLo = cutv;
                sHi = L + (bstar + 1) * w;
            }
        }
        __syncthreads();
    }

    const float cutoff = sCut;
    for (int s = tid; s < total_slots; s += TA) {
        float v = sval[s];
        if (v > conf && v >= cutoff) {
            int ps = atomicAdd(&sGc, 1);
            if (ps < GCAP) {
                int cc = s / MAXK;
                unsigned flat = (unsigned)(cc * n + g_kb[s]);
                gkey[ps] = ((unsigned long long)__float_as_uint(v) << 32)
                           | (unsigned)(~flat);    // ties: lower flat first
            }
        }
    }
    __syncthreads();
    const int G = min(sGc, GCAP);
    for (int p = G + tid; p < GCAP; p += TA) gkey[p] = 0ULL;
    __syncthreads();

    // shfl-fused bitonic sort, fixed P=512
    const int PB = GCAP;
    for (int k = 2; k <= PB; k <<= 1) {
        for (int j = k >> 1; j >= 256; j >>= 1) {
            for (int p = tid; p < PB; p += TA) {
                int q = p ^ j;
                if (q > p) {
                    unsigned long long a = gkey[p], b = gkey[q];
                    bool dirDesc = ((p & k) == 0);
                    if (dirDesc ? (a < b) : (a > b)) { gkey[p] = b; gkey[q] = a; }
                }
            }
            __syncthreads();
        }
        for (int base = tid * 8; base < PB; base += TA * 8) {
            unsigned long long v[8];
            #pragma unroll
            for (int a = 0; a < 8; a++) v[a] = gkey[base + a];
            const bool up = ((base & k) == 0);
            int jtop = (k >> 1 < 128) ? (k >> 1) : 128;
            for (int j = jtop; j >= 8; j >>= 1) {
                int tj = j >> 3;
                bool keepMax = (up == ((tid & tj) == 0));
                #pragma unroll
                for (int a = 0; a < 8; a++) {
                    unsigned long long pv = __shfl_xor_sync(FULL, v[a], tj);
                    if (keepMax ? (pv > v[a]) : (pv < v[a])) v[a] = pv;
                }
            }
            int j0 = (k >> 1 < 4) ? (k >> 1) : 4;
            for (int j = j0; j > 0; j >>= 1) {
                #pragma unroll
                for (int a = 0; a < 8; a++) {
                    int b = a ^ j;
                    if (b > a) {
                        bool dd = (((base + a) & k) == 0);
                        unsigned long long xx = v[a], yy = v[b];
                        if (dd ? (xx < yy) : (xx > yy)) { v[a] = yy; v[b] = xx; }
                    }
                }
            }
            #pragma unroll
            for (int a = 0; a < 8; a++) gkey[base + a] = v[a];
        }
        __syncthreads();
    }

    // outputs: preds [300,5] then labels [300] (as float)
    const float* bbf = (const float*)bb4;
    for (int i = tid; i < MAXK; i += TA) {
        bool valid = (i < G) && (gkey[i] != 0ULL);
        if (valid) {
            unsigned long long kk = gkey[i];
            float    s    = __uint_as_float((unsigned)(kk >> 32));
            unsigned flat = ~(unsigned)kk;
            int cc  = flat / n;
            int box = flat - cc * n;
            out[i * 5 + 0] = bbf[box * 4 + 0];
            out[i * 5 + 1] = bbf[box * 4 + 1];
            out[i * 5 + 2] = bbf[box * 4 + 2];
            out[i * 5 + 3] = bbf[box * 4 + 3];
            out[i * 5 + 4] = s;
            out[MAXK * 5 + i] = (float)(cc + 1);
        } else {
            out[i * 5 + 0] = 0.f; out[i * 5 + 1] = 0.f;
            out[i * 5 + 2] = 0.f; out[i * 5 + 3] = 0.f;
            out[i * 5 + 4] = 0.f;
            out[MAXK * 5 + i] = -1.0f;
        }
    }
}

// ---------------- launch ----------------
extern "C" void kernel_launch(void* const* d_in, const int* in_sizes, int n_in,
                              void* d_out, int out_size)
{
    const float* bboxes = (const float*)d_in[0];
    const float* scores = (const float*)d_in[1];
    const float* confp  = (const float*)d_in[2];
    const float* nmsp   = (const float*)d_in[3];

    int n  = in_sizes[0] / 4;
    int c  = in_sizes[1] / n;
    int nc = c - 1;

    const int smemF = 109568;
    static bool attr_set = false;
    if (!attr_set) {
        cudaFuncSetAttribute(fused_kernel,
                             cudaFuncAttributeMaxDynamicSharedMemorySize, smemF);
        attr_set = true;
    }

    dim3 tgrid((c + 31) / 32, (n + 31) / 32), tblk(32, 8);
    transpose_kernel<<<tgrid, tblk>>>(scores, n, c);
    fused_kernel<<<nc, TA, smemF>>>((const float4*)bboxes, confp, nmsp,
                                    (float*)d_out, n, nc);
}

// round 11
// speedup vs baseline: 2.3614x; 2.3614x over previous
#include <cuda_runtime.h>
#include <math_constants.h>
#include <stdint.h>

// MulticlassNMS v5 — global-threshold pruned NMS.
// K1: transpose scores -> g_T (coalesced per-class rows) + global 2048-bin
//     histogram of valid scores; last block derives threshold t (~1024 survivors).
// K2: 1 block/class: compact (score > t), warp-sort (tiny M), single-chunk
//     greedy NMS, append packed keys; last block: (rare) refine, sort 2048,
//     write preds+labels. Exact fallback: if total keeps < 300 and t > conf,
//     last block reruns full NMS for all classes at t=conf (never triggers
//     in practice; guarantees exactness).

#define MAXCLS  128
#define MAXK    300
#define TA      512
#define SBOXN   1024
#define GCAP2   2048
#define HBINS   2048
#define TTARGET 1024
#define TMAXCUM 4096

__device__ float              g_T[MAXCLS * 8192];
__device__ unsigned long long g_ck[MAXCLS * MAXK];
__device__ int                g_hist[HBINS];
__device__ float              g_thresh;
__device__ unsigned           g_arrive1, g_arrive2;
__device__ int                g_compact;

// exact IoU>thr: multiply filter, __fdiv_rn fallback in ~1e-4 boundary band
__device__ __forceinline__ bool iou_gt(const float4 a, float aa,
                                       const float4 b, float ba,
                                       float thr, float thrLo, float thrHi)
{
    float ix1 = fmaxf(a.x, b.x), iy1 = fmaxf(a.y, b.y);
    float ix2 = fminf(a.z, b.z), iy2 = fminf(a.w, b.w);
    float iw = ix2 - ix1, ih = iy2 - iy1;
    if (iw <= 0.f || ih <= 0.f) return false;
    float inter = iw * ih;
    float u = (aa + ba) - inter;
    if (inter > thrHi * u) return true;
    if (inter < thrLo * u) return false;
    return __fdiv_rn(inter, u) > thr;
}

// ================= K1: transpose + histogram + threshold ==================
__global__ void prep_kernel(const float* __restrict__ scores,
                            const float* __restrict__ confp,
                            int n, int c, int nblocks)
{
    __shared__ float tile[32][33];
    __shared__ int   hist[HBINS];
    __shared__ unsigned sLast;
    const float conf = *confp;
    const int tx = threadIdx.x, ty = threadIdx.y;
    const int tid = ty * 32 + tx;

    for (int b = tid; b < HBINS; b += 256) hist[b] = 0;
    int j0 = blockIdx.x * 32, i0 = blockIdx.y * 32;
    #pragma unroll
    for (int k = 0; k < 32; k += 8) {
        int i = i0 + ty + k, j = j0 + tx;
        tile[ty + k][tx] = (i < n && j < c) ? scores[(size_t)i * c + j] : 0.f;
    }
    __syncthreads();
    const float scale = (conf < 1.0f) ? (HBINS / (1.0f - conf)) : 0.f;
    #pragma unroll
    for (int k = 0; k < 32; k += 8) {
        int jt = j0 + ty + k, it = i0 + tx;
        if (jt >= 1 && jt < c && it < n) {
            float v = tile[tx][ty + k];
            g_T[(size_t)(jt - 1) * n + it] = v;
            if (v > conf && conf < 1.0f) {
                int b = (int)((v - conf) * scale);
                b = max(0, min(HBINS - 1, b));
                atomicAdd(&hist[b], 1);
            }
        }
    }
    __syncthreads();
    for (int b = tid; b < HBINS; b += 256) {
        int h = hist[b];
        if (h) atomicAdd(&g_hist[b], h);
    }
    __threadfence();
    __syncthreads();
    if (tid == 0)
        sLast = (atomicAdd(&g_arrive1, 1) == (unsigned)(nblocks - 1)) ? 1u : 0u;
    __syncthreads();
    if (!sLast) return;

    // stage global hist -> shared, then scan (thread 0)
    for (int b = tid; b < HBINS; b += 256) hist[b] = g_hist[b];
    __syncthreads();
    if (tid == 0) {
        float t = conf;
        if (conf < 1.0f) {
            int cum = 0, bsel = -1;
            for (int b = HBINS - 1; b >= 0; b--) {
                int h = hist[b];
                if (cum + h >= TTARGET) {
                    bsel = (cum + h <= TMAXCUM) ? b : b + 1;
                    break;
                }
                cum += h;
            }
            if (bsel > 0) {
                float step = (1.0f - conf) / HBINS;
                float tt = conf + bsel * step;
                if (tt > conf) t = tt;
            }
        }
        g_thresh  = t;
        g_compact = 0;
        g_arrive1 = 0;   // reset for next replay
    }
}

// ================= per-class NMS (device function) ========================
// Returns nKept; kkey[0..nKept) filled with (scorebits<<32)|~flat.
// Ends with __syncthreads() (kkey visible block-wide).
__device__ int nms_class_dev(int cls, float tcut, int n,
                             float thr, float thrLo, float thrHi,
                             const float4* __restrict__ bb4,
                             unsigned long long* skey, float4* sbox, float* sarea,
                             float4* kbox, float* karea, unsigned long long* kkey,
                             float4* cbox, float* carea,
                             unsigned* sIntra, unsigned* snzw, unsigned* sSup32)
{
    __shared__ int wsum[16];
    __shared__ unsigned long long sKeptMask;
    const int tid = threadIdx.x, wid = tid >> 5, lane = tid & 31;
    const unsigned FULL = 0xffffffffu;
    const float* Tc = g_T + (size_t)cls * n;

    // ---- compact: count -> scan -> scatter (coalesced) ----
    int cnt = 0;
    for (int i = tid; i < n; i += TA) cnt += (Tc[i] > tcut) ? 1 : 0;
    int x = cnt;
    #pragma unroll
    for (int o = 1; o < 32; o <<= 1) {
        int y = __shfl_up_sync(FULL, x, o);
        if (lane >= o) x += y;
    }
    if (lane == 31) wsum[wid] = x;
    __syncthreads();
    if (tid < 32) {
        int w = (tid < 16) ? wsum[tid] : 0;
        #pragma unroll
        for (int o = 1; o < 16; o <<= 1) {
            int y = __shfl_up_sync(FULL, w, o);
            if (tid >= o) w += y;
        }
        if (tid < 16) wsum[tid] = w;
    }
    __syncthreads();
    int off = x - cnt + ((wid > 0) ? wsum[wid - 1] : 0);
    const int M = wsum[15];
    for (int i = tid; i < n; i += TA) {
        float s = Tc[i];
        if (s > tcut) {
            skey[off] = ((unsigned long long)__float_as_uint(s) << 32) | (unsigned)i;
            off++;
        }
    }
    __syncthreads();

    // ---- sort desc (ties -> larger idx first) ----
    if (M <= 32) {
        if (wid == 0) {
            unsigned long long v = (lane < M) ? skey[lane] : 0ULL;
            #pragma unroll
            for (int k = 2; k <= 32; k <<= 1) {
                #pragma unroll
                for (int j = 16; j > 0; j >>= 1) {
                    if (j < k) {
                        unsigned long long pv = __shfl_xor_sync(FULL, v, j);
                        bool keepMax = (((lane & k) == 0) == ((lane & j) == 0));
                        bool pvBig = pv > v;
                        if (keepMax == pvBig) v = pv;
                    }
                }
            }
            skey[lane] = v;
        }
        __syncthreads();
    } else {
        int P = 256; while (P < M) P <<= 1;
        for (int p = M + tid; p < P; p += TA) skey[p] = 0ULL;
        __syncthreads();
        for (int k = 2; k <= P; k <<= 1) {
            for (int j = k >> 1; j >= 256; j >>= 1) {
                for (int p = tid; p < P; p += TA) {
                    int q = p ^ j;
                    if (q > p) {
                        unsigned long long a = skey[p], b = skey[q];
                        bool dirDesc = ((p & k) == 0);
                        if (dirDesc ? (a < b) : (a > b)) { skey[p] = b; skey[q] = a; }
                    }
                }
                __syncthreads();
            }
            for (int base = tid * 8; base < P; base += TA * 8) {
                unsigned long long v[8];
                #pragma unroll
                for (int a = 0; a < 8; a++) v[a] = skey[base + a];
                const bool up = ((base & k) == 0);
                int jtop = (k >> 1 < 128) ? (k >> 1) : 128;
                for (int j = jtop; j >= 8; j >>= 1) {
                    int tj = j >> 3;
                    bool keepMax = (up == ((tid & tj) == 0));
                    #pragma unroll
                    for (int a = 0; a < 8; a++) {
                        unsigned long long pv = __shfl_xor_sync(FULL, v[a], tj);
                        if (keepMax ? (pv > v[a]) : (pv < v[a])) v[a] = pv;
                    }
                }
                int j0 = (k >> 1 < 4) ? (k >> 1) : 4;
                for (int j = j0; j > 0; j >>= 1) {
                    #pragma unroll
                    for (int a = 0; a < 8; a++) {
                        int b = a ^ j;
                        if (b > a) {
                            bool dd = (((base + a) & k) == 0);
                            unsigned long long xx = v[a], yy = v[b];
                            if (dd ? (xx < yy) : (xx > yy)) { v[a] = yy; v[b] = xx; }
                        }
                    }
                }
                #pragma unroll
                for (int a = 0; a < 8; a++) skey[base + a] = v[a];
            }
            __syncthreads();
        }
    }

    // ---- prefetch boxes ----
    const int PF = min(M, SBOXN);
    for (int p = tid; p < PF; p += TA) {
        float4 b = bb4[(unsigned)(skey[p] & 0xffffffffu)];
        sbox[p]  = b;
        sarea[p] = (b.z - b.x) * (b.w - b.y);
    }
    __syncthreads();

    // ---- chunked greedy NMS (64-wide) ----
    int pos = 0, nKept = 0;
    while (pos < M && nKept < MAXK) {
        const int nv = min(64, M - pos);
        if (tid < 64) {
            int cl2 = pos + tid;
            float4 cb = make_float4(0.f, 0.f, 0.f, 0.f);
            if (cl2 < M)
                cb = (cl2 < PF) ? sbox[cl2]
                                : bb4[(unsigned)(skey[cl2] & 0xffffffffu)];
            cbox[tid]  = cb;
            carea[tid] = (cb.z - cb.x) * (cb.w - cb.y);
            if (tid < 2)  sSup32[tid] = 0;
            if (tid < 16) snzw[tid]   = 0;
        }
        __syncthreads();
        {
            int cg = wid & 1;
            int cc = (cg << 5) | lane;
            float4 cb = cbox[cc];
            float  ca = carea[cc];
            bool sup = false;
            for (int k2 = wid >> 1; k2 < nKept; k2 += 8)
                sup |= iou_gt(kbox[k2], karea[k2], cb, ca, thr, thrLo, thrHi);
            unsigned bm = __ballot_sync(FULL, sup);
            if (lane == 0 && bm) atomicOr(&sSup32[cg], bm);

            unsigned nzm = 0;
            #pragma unroll
            for (int r0 = 0; r0 < 4; r0++) {
                int r = (wid << 2) + r0;
                float4 rb = cbox[r];
                float  ra = carea[r];
                #pragma unroll
                for (int g = 0; g < 2; g++) {
                    int col = (g << 5) | lane;
                    bool pr = (col > r) &&
                              iou_gt(rb, ra, cbox[col], carea[col], thr, thrLo, thrHi);
                    unsigned w2 = __ballot_sync(FULL, pr);
                    if (lane == 0) {
                        sIntra[r * 2 + g] = w2;
                        if (w2) nzm |= 1u << (r0 * 2 + g);
                    }
                }
            }
            if (lane == 0) snzw[wid] = nzm;
        }
        __syncthreads();

        if (tid == 0) {
            unsigned long long valid = (nv >= 64) ? ~0ULL : ((1ULL << nv) - 1ULL);
            unsigned long long sup = (((unsigned long long)sSup32[1] << 32) |
                                       sSup32[0]) | ~valid;
            unsigned long long nz = 0;
            #pragma unroll
            for (int w = 0; w < 16; w++) {
                unsigned mm = snzw[w];
                unsigned rowbits = 0;
                #pragma unroll
                for (int r0 = 0; r0 < 4; r0++)
                    if (mm & (3u << (2 * r0))) rowbits |= 1u << r0;
                nz |= (unsigned long long)rowbits << (4 * w);
            }
            unsigned long long kept = 0;
            int prev = 0;
            while (nz) {
                int i = __ffsll((long long)nz) - 1;
                nz &= nz - 1;
                unsigned long long upto  = (i >= 63) ? ~0ULL : ((1ULL << (i + 1)) - 1ULL);
                unsigned long long fromp = (~0ULL) << prev;
                kept |= ~sup & upto & fromp;
                if (!((sup >> i) & 1ULL)) {
                    unsigned long long row =
                        (((unsigned long long)sIntra[2 * i + 1]) << 32) | sIntra[2 * i];
                    sup |= row;
                }
                prev = i + 1;
            }
            unsigned long long fromp = (prev >= 64) ? 0ULL : ((~0ULL) << prev);
            kept |= ~sup & fromp;
            sKeptMask = kept & valid;
        }
        __syncthreads();

        unsigned long long kept = sKeptMask;
        if (tid < 64) {
            bool mk = (kept >> tid) & 1ULL;
            int before = __popcll(kept & ((1ULL << tid) - 1ULL));
            int myPos  = nKept + before;
            if (mk && myPos < MAXK) {
                kbox[myPos]  = cbox[tid];
                karea[myPos] = carea[tid];
                unsigned long long kk = skey[pos + tid];
                unsigned idx  = (unsigned)kk;
                unsigned flat = (unsigned)(cls * n) + idx;
                kkey[myPos] = (kk & 0xffffffff00000000ULL) | (unsigned)(~flat);
            }
        }
        int nk = nKept + __popcll(kept);
        nKept = (nk > MAXK) ? MAXK : nk;
        pos  += 64;
        __syncthreads();
    }
    return nKept;
}

// ================= finalize: top-300 + output (one block) =================
__device__ void finalize_out(int G, int n, float conf,
                             const float* __restrict__ bbf, float* __restrict__ out,
                             unsigned long long* gkey, int* hist, int* schunk)
{
    __shared__ int   sGc, sDone, sAbove, smaxbits;
    __shared__ float sLo, sHi, sCut;
    const int tid = threadIdx.x, lane = tid & 31;
    const unsigned FULL = 0xffffffffu;

    if (tid == 0) { sGc = 0; sDone = 0; sAbove = 0; smaxbits = 0; }
    __syncthreads();

    float cutoff = -CUDART_INF_F;
    if (G > GCAP2) {
        int mb = 0;
        for (int s = tid; s < G; s += TA) mb = max(mb, (int)(unsigned)(g_ck[s] >> 32));
        for (int o = 16; o; o >>= 1) mb = max(mb, __shfl_xor_sync(FULL, mb, o));
        if (lane == 0) atomicMax(&smaxbits, mb);
        __syncthreads();
        if (tid == 0) {
            sLo = conf;
            sHi = __int_as_float(smaxbits) * 1.0000002f + 1e-30f;
        }
        __syncthreads();
        for (int lev = 0; lev < 8; lev++) {
            if (sDone) break;
            for (int b = tid; b < 2048; b += TA) hist[b] = 0;
            __syncthreads();
            float L = sLo, H = sHi;
            float scale = 2048.0f / (H - L);
            for (int s = tid; s < G; s += TA) {
                float v = __uint_as_float((unsigned)(g_ck[s] >> 32));
                if (v >= L && v < H) {
                    int b = (int)((v - L) * scale);
                    b = max(0, min(2047, b));
                    atomicAdd(&hist[b], 1);
                }
            }
            __syncthreads();
            if (tid < 256) {
                int sum = 0;
                for (int b = tid * 8; b < tid * 8 + 8; b++) sum += hist[b];
                schunk[tid] = sum;
            }
            __syncthreads();
            if (tid == 0) {
                int acc = sAbove, bstar = -1;
                for (int ch = 255; ch >= 0 && bstar < 0; ch--) {
                    if (acc + schunk[ch] < MAXK) { acc += schunk[ch]; }
                    else {
                        for (int b = ch * 8 + 7; b >= ch * 8; b--) {
                            if (acc + hist[b] < MAXK) acc += hist[b];
                            else { bstar = b; break; }
                        }
                    }
                }
                float w    = (H - L) / 2048.0f;
                float cutv = L + bstar * w;
                bool collapsed = !(w > 0.f) || (L + w == L);
                if (acc + hist[bstar] <= GCAP2 || lev == 7 || collapsed) {
                    float cut = cutv;
                    if (cut > 0.f) cut = __uint_as_float(__float_as_uint(cut) - 2);
                    sCut = cut; sDone = 1;
                } else {
                    sAbove = acc;
                    sLo = cutv;
                    sHi = L + (bstar + 1) * w;
                }
            }
            __syncthreads();
        }
        cutoff = sCut;
    }

    const bool takeAll = (G <= GCAP2);
    for (int s = tid; s < G; s += TA) {
        unsigned long long kk = g_ck[s];
        float v = __uint_as_float((unsigned)(kk >> 32));
        if (takeAll || v >= cutoff) {
            int ps = atomicAdd(&sGc, 1);
            if (ps < GCAP2) gkey[ps] = kk;
        }
    }
    __syncthreads();
    const int GG = min(sGc, GCAP2);
    for (int p = GG + tid; p < GCAP2; p += TA) gkey[p] = 0ULL;
    __syncthreads();

    // bitonic sort desc, P=2048, shfl-fused
    const int P = GCAP2;
    for (int k = 2; k <= P; k <<= 1) {
        for (int j = k >> 1; j >= 256; j >>= 1) {
            for (int p = tid; p < P; p += TA) {
                int q = p ^ j;
                if (q > p) {
                    unsigned long long a = gkey[p], b = gkey[q];
                    bool dirDesc = ((p & k) == 0);
                    if (dirDesc ? (a < b) : (a > b)) { gkey[p] = b; gkey[q] = a; }
                }
            }
            __syncthreads();
        }
        for (int base = tid * 8; base < P; base += TA * 8) {
            unsigned long long v[8];
            #pragma unroll
            for (int a = 0; a < 8; a++) v[a] = gkey[base + a];
            const bool up = ((base & k) == 0);
            int jtop = (k >> 1 < 128) ? (k >> 1) : 128;
            for (int j = jtop; j >= 8; j >>= 1) {
                int tj = j >> 3;
                bool keepMax = (up == ((tid & tj) == 0));
                #pragma unroll
                for (int a = 0; a < 8; a++) {
                    unsigned long long pv = __shfl_xor_sync(FULL, v[a], tj);
                    if (keepMax ? (pv > v[a]) : (pv < v[a])) v[a] = pv;
                }
            }
            int j0 = (k >> 1 < 4) ? (k >> 1) : 4;
            for (int j = j0; j > 0; j >>= 1) {
                #pragma unroll
                for (int a = 0; a < 8; a++) {
                    int b = a ^ j;
                    if (b > a) {
                        bool dd = (((base + a) & k) == 0);
                        unsigned long long xx = v[a], yy = v[b];
                        if (dd ? (xx < yy) : (xx > yy)) { v[a] = yy; v[b] = xx; }
                    }
                }
            }
            #pragma unroll
            for (int a = 0; a < 8; a++) gkey[base + a] = v[a];
        }
        __syncthreads();
    }

    for (int i = tid; i < MAXK; i += TA) {
        bool valid = (i < GG) && (gkey[i] != 0ULL);
        if (valid) {
            unsigned long long kk = gkey[i];
            float    s    = __uint_as_float((unsigned)(kk >> 32));
            unsigned flat = ~(unsigned)kk;
            int cc  = flat / n;
            int box = flat - cc * n;
            out[i * 5 + 0] = bbf[box * 4 + 0];
            out[i * 5 + 1] = bbf[box * 4 + 1];
            out[i * 5 + 2] = bbf[box * 4 + 2];
            out[i * 5 + 3] = bbf[box * 4 + 3];
            out[i * 5 + 4] = s;
            out[MAXK * 5 + i] = (float)(cc + 1);
        } else {
            out[i * 5 + 0] = 0.f; out[i * 5 + 1] = 0.f;
            out[i * 5 + 2] = 0.f; out[i * 5 + 3] = 0.f;
            out[i * 5 + 4] = 0.f;
            out[MAXK * 5 + i] = -1.0f;
        }
    }
}

// ================= K2: per-class NMS + last-block finalize ================
__global__ __launch_bounds__(TA)
void nms_kernel(const float4* __restrict__ bb4,
                const float* __restrict__ confp,
                const float* __restrict__ nmsp,
                float* __restrict__ out,
                int n, int nc)
{
    extern __shared__ unsigned char smraw[];
    unsigned long long* skey   = (unsigned long long*)smraw;          // 8192
    float4*             sbox   = (float4*)(smraw + 65536);            // 1024
    float4*             kbox   = (float4*)(smraw + 81920);            // 304
    float4*             cbox   = (float4*)(smraw + 86784);            // 64
    float*              sarea  = (float*)(smraw + 87808);             // 1024
    float*              karea  = (float*)(smraw + 91904);             // 304
    unsigned long long* kkey   = (unsigned long long*)(smraw + 93120);// 304
    float*              carea  = (float*)(smraw + 95552);             // 64
    unsigned*           sIntra = (unsigned*)(smraw + 95808);          // 128
    unsigned*           snzw   = (unsigned*)(smraw + 96320);          // 16
    unsigned*           sSup32 = (unsigned*)(smraw + 96384);          // 2
    // finalize overlays
    unsigned long long* gkey   = (unsigned long long*)smraw;          // 2048
    int*                hist   = (int*)(smraw + 65536);               // 2048
    int*                schunk = (int*)(smraw + 73728);               // 256

    __shared__ int      sBase;
    __shared__ unsigned sLast;

    const int tid = threadIdx.x;
    const int cls = blockIdx.x;
    const float conf  = *confp;
    const float thr   = *nmsp;
    const float thrLo = thr * 0.9999f;
    const float thrHi = thr * 1.0001f;
    const float t = g_thresh;

    int nKept = nms_class_dev(cls, t, n, thr, thrLo, thrHi, bb4,
                              skey, sbox, sarea, kbox, karea, kkey,
                              cbox, carea, sIntra, snzw, sSup32);

    if (tid == 0) sBase = atomicAdd(&g_compact, nKept);
    __syncthreads();
    for (int i = tid; i < nKept; i += TA) g_ck[sBase + i] = kkey[i];
    __threadfence();
    __syncthreads();
    if (tid == 0)
        sLast = (atomicAdd(&g_arrive2, 1) == (unsigned)(nc - 1)) ? 1u : 0u;
    __syncthreads();
    if (!sLast) return;
    __threadfence();

    int G = g_compact;
    if (G < MAXK && __float_as_uint(t) != __float_as_uint(conf)) {
        // exact fallback: rerun all classes without threshold (never expected)
        int base = 0;
        for (int cc = 0; cc < nc; cc++) {
            int kc = nms_class_dev(cc, conf, n, thr, thrLo, thrHi, bb4,
                                   skey, sbox, sarea, kbox, karea, kkey,
                                   cbox, carea, sIntra, snzw, sSup32);
            for (int i = tid; i < kc; i += TA) g_ck[base + i] = kkey[i];
            base += kc;
            __syncthreads();
        }
        G = base;
    }

    // reset for next replay
    if (tid == 0) g_arrive2 = 0;
    for (int b = tid; b < HBINS; b += TA) g_hist[b] = 0;

    finalize_out(G, n, conf, (const float*)bb4, out, gkey, hist, schunk);
}

// ================= launch =================================================
extern "C" void kernel_launch(void* const* d_in, const int* in_sizes, int n_in,
                              void* d_out, int out_size)
{
    const float* bboxes = (const float*)d_in[0];
    const float* scores = (const float*)d_in[1];
    const float* confp  = (const float*)d_in[2];
    const float* nmsp   = (const float*)d_in[3];

    int n  = in_sizes[0] / 4;
    int c  = in_sizes[1] / n;
    int nc = c - 1;

    const int smemF = 96512;
    static bool attr_set = false;
    if (!attr_set) {
        cudaFuncSetAttribute(nms_kernel,
                             cudaFuncAttributeMaxDynamicSharedMemorySize, smemF);
        attr_set = true;
    }

    dim3 tgrid((c + 31) / 32, (n + 31) / 32), tblk(32, 8);
    prep_kernel<<<tgrid, tblk>>>(scores, confp, n, c, tgrid.x * tgrid.y);
    nms_kernel<<<nc, TA, smemF>>>((const float4*)bboxes, confp, nmsp,
                                  (float*)d_out, n, nc);
}